// round 10
// baseline (speedup 1.0000x reference)
#include <cuda_runtime.h>
#include <cuda_bf16.h>
#include <cstdint>

// PARAFAC / CP reconstruction: out[a,b,c] = sum_k f0[k,a]*f1[k,b]*f2[k,c]
// A=B=C=512, RANK=16, fp32 out (536 MB stores).
//
// Round-10 = round-9 resubmit (infra failure, kernel never ran):
// mma.sync split-bf16 (validated round 8, rel_err 4.4e-6) + FIXED EPILOGUE:
//   - accumulate 4 n-blocks, then 4x4 float2 XOR-transpose within each 4-lane
//     q-group (2 shfl_xor stages) -> each lane holds 8 CONSECUTIVE c
//     -> 2x STG.128 per row -> 2 wf/128B stores (round 8 scattered at ~5 wf/128B)
//   - B-fragments preloaded into 64 regs from a per-(c,q) 16B-quad SMEM layout
//     (1 conflict-free LDS.128 per m-block), reused across 64 b per warp
//   - fma pipe ~empty; L1 ~2.5 wf/128B. Decisive test of the 5.6 TB/s write wall.
// Only delta vs round 9: 64-bit shuffles written as explicit 2x 32-bit shfl.

#define A_DIM 512
#define B_DIM 512
#define C_DIM 512
#define RANK  16
#define CTILE 128        // c per block (16 n-blocks)
#define BTILE 256        // b per block = 4 warps x 64 b
#define NTHREADS 128

typedef unsigned long long ull;

__device__ __forceinline__ uint32_t bfpack(__nv_bfloat16 e0, __nv_bfloat16 e1) {
    __nv_bfloat162 p; p.x = e0; p.y = e1;
    return *reinterpret_cast<uint32_t*>(&p);
}
__device__ __forceinline__ void split_bf16(float v, __nv_bfloat16& hi, __nv_bfloat16& lo) {
    hi = __float2bfloat16(v);
    lo = __float2bfloat16(v - __bfloat162float(hi));
}
__device__ __forceinline__ void mma16816(float& d0, float& d1, float& d2, float& d3,
                                         uint32_t a0, uint32_t a1, uint32_t a2, uint32_t a3,
                                         uint32_t b0, uint32_t b1) {
    asm volatile(
        "mma.sync.aligned.m16n8k16.row.col.f32.bf16.bf16.f32 "
        "{%0,%1,%2,%3}, {%4,%5,%6,%7}, {%8,%9}, {%0,%1,%2,%3};"
        : "+f"(d0), "+f"(d1), "+f"(d2), "+f"(d3)
        : "r"(a0), "r"(a1), "r"(a2), "r"(a3), "r"(b0), "r"(b1));
}
__device__ __forceinline__ ull pk(float x, float y) {
    float2 p = make_float2(x, y);
    return *reinterpret_cast<ull*>(&p);
}
// 64-bit xor-shuffle via two 32-bit SHFLs (explicit, compiler-version proof)
__device__ __forceinline__ ull shfl_xor64(ull v, int m) {
    uint32_t lo = (uint32_t)v, hi = (uint32_t)(v >> 32);
    lo = __shfl_xor_sync(0xFFFFFFFFu, lo, m);
    hi = __shfl_xor_sync(0xFFFFFFFFu, hi, m);
    return ((ull)hi << 32) | lo;
}

__global__ __launch_bounds__(NTHREADS, 3)
void parafac_mma_kernel(const float* __restrict__ f0,
                        const float* __restrict__ f1,
                        const float* __restrict__ f2,
                        float* __restrict__ out)
{
    // F2 split tile, per (c, qslot) 16-B quad: {bh0, bh1, bl0, bl1}
    //   bh0 = hi(k=2q,2q+1)  bh1 = hi(k=2q+8,2q+9)  bl0/bl1 = lo(same)
    __shared__ __align__(16) unsigned char F2s[CTILE * 64];   // 8 KB

    const int a  = blockIdx.z;
    const int b0 = blockIdx.y * BTILE;
    const int c0 = blockIdx.x * CTILE;
    const int t  = threadIdx.x;
    const int w    = t >> 5;
    const int lane = t & 31;
    const int q    = lane & 3;
    const int r    = lane >> 2;

    // ---- stage F2 split tile (once per block; amortized over 128 KB output) ----
    for (int i = t; i < CTILE * RANK; i += NTHREADS) {
        int k  = i >> 7;
        int cc = i & 127;            // contiguous over c -> coalesced LDG
        float v = f2[k * C_DIM + c0 + cc];
        __nv_bfloat16 hi, lo;
        split_bf16(v, hi, lo);
        int base = cc * 64 + ((k & 7) >> 1) * 16 + ((k >> 3) & 1) * 4 + (k & 1) * 2;
        *reinterpret_cast<__nv_bfloat16*>(F2s + base)     = hi;
        *reinterpret_cast<__nv_bfloat16*>(F2s + base + 8) = lo;
    }
    __syncthreads();

    // ---- preload ALL B-fragments to registers: one LDS.128 per m (conflict-free) ----
    uint4 bfr[16];
#pragma unroll
    for (int m = 0; m < 16; m++) {
        bfr[m] = *reinterpret_cast<const uint4*>(F2s + (8 * m + r) * 64 + q * 16);
    }

    float* oblk = out + (size_t)a * (B_DIM * C_DIM) + (size_t)c0;

    // ---- warp covers 64 b via 4 sub-tiles of 16, reusing bfr ----
#pragma unroll 1
    for (int sub = 0; sub < 4; sub++) {
        const int br0 = b0 + w * 64 + sub * 16 + r;
        const int br1 = br0 + 8;

        // A fragments (g side) per documented m16n8k16 coords (validated round 8)
        uint32_t ah[4], al[4];
        {
            const int ks[2] = { 2 * q, 2 * q + 8 };
#pragma unroll
            for (int h = 0; h < 2; h++) {
                int k0 = ks[h], k1 = ks[h] + 1;
                float ga0 = f0[k0 * A_DIM + a] * f1[k0 * B_DIM + br0];
                float ga1 = f0[k1 * A_DIM + a] * f1[k1 * B_DIM + br0];
                float gb0 = f0[k0 * A_DIM + a] * f1[k0 * B_DIM + br1];
                float gb1 = f0[k1 * A_DIM + a] * f1[k1 * B_DIM + br1];
                __nv_bfloat16 h0, l0, h1, l1;
                split_bf16(ga0, h0, l0); split_bf16(ga1, h1, l1);
                ah[2 * h + 0] = bfpack(h0, h1);
                al[2 * h + 0] = bfpack(l0, l1);
                split_bf16(gb0, h0, l0); split_bf16(gb1, h1, l1);
                ah[2 * h + 1] = bfpack(h0, h1);
                al[2 * h + 1] = bfpack(l0, l1);
            }
        }

        float* row0 = oblk + (size_t)br0 * C_DIM;
        float* row1 = oblk + (size_t)br1 * C_DIM;

#pragma unroll
        for (int mg = 0; mg < 4; mg++) {
            // compute 4 n-blocks; vlo[i] = (D[r][c],D[r][c+1]) for m = 4mg+i, c = 8m+2q
            ull vlo[4], vhi[4];
#pragma unroll
            for (int i = 0; i < 4; i++) {
                const uint4 bm = bfr[4 * mg + i];
                float d0 = 0.f, d1 = 0.f, d2 = 0.f, d3 = 0.f;
                mma16816(d0, d1, d2, d3, ah[0], ah[1], ah[2], ah[3], bm.x, bm.y); // Ah*Bh
                mma16816(d0, d1, d2, d3, al[0], al[1], al[2], al[3], bm.x, bm.y); // Al*Bh
                mma16816(d0, d1, d2, d3, ah[0], ah[1], ah[2], ah[3], bm.z, bm.w); // Ah*Bl
                vlo[i] = pk(d0, d1);
                vhi[i] = pk(d2, d3);
            }

            // 4x4 float2 transpose within each 4-lane q-group: w_q[i] = v_i[q]
            //   stage s: t[i] = ((i^q)&s) ? shfl_xor(v[i^s], s) : v[i]
#pragma unroll
            for (int s = 1; s <= 2; s <<= 1) {
                ull tlo[4], thi[4];
#pragma unroll
                for (int i = 0; i < 4; i++) {
                    ull sl = shfl_xor64(vlo[i ^ s], s);
                    ull sh = shfl_xor64(vhi[i ^ s], s);
                    bool sw = ((i ^ q) & s) != 0;
                    tlo[i] = sw ? sl : vlo[i];
                    thi[i] = sw ? sh : vhi[i];
                }
#pragma unroll
                for (int i = 0; i < 4; i++) { vlo[i] = tlo[i]; vhi[i] = thi[i]; }
            }

            // lane q now holds c = 8*(4mg+q) + {0..7} as 4 float2 (in order)
            const int c = 8 * (4 * mg + q);
            float2 l0 = *reinterpret_cast<float2*>(&vlo[0]);
            float2 l1 = *reinterpret_cast<float2*>(&vlo[1]);
            float2 l2 = *reinterpret_cast<float2*>(&vlo[2]);
            float2 l3 = *reinterpret_cast<float2*>(&vlo[3]);
            float2 h0 = *reinterpret_cast<float2*>(&vhi[0]);
            float2 h1 = *reinterpret_cast<float2*>(&vhi[1]);
            float2 h2 = *reinterpret_cast<float2*>(&vhi[2]);
            float2 h3 = *reinterpret_cast<float2*>(&vhi[3]);
            *reinterpret_cast<float4*>(row0 + c)     = make_float4(l0.x, l0.y, l1.x, l1.y);
            *reinterpret_cast<float4*>(row0 + c + 4) = make_float4(l2.x, l2.y, l3.x, l3.y);
            *reinterpret_cast<float4*>(row1 + c)     = make_float4(h0.x, h0.y, h1.x, h1.y);
            *reinterpret_cast<float4*>(row1 + c + 4) = make_float4(h2.x, h2.y, h3.x, h3.y);
        }
    }
}

extern "C" void kernel_launch(void* const* d_in, const int* in_sizes, int n_in,
                              void* d_out, int out_size)
{
    const float* f0 = (const float*)d_in[0];
    const float* f1 = (const float*)d_in[1];
    const float* f2 = (const float*)d_in[2];
    float* out = (float*)d_out;

    dim3 grid(C_DIM / CTILE, B_DIM / BTILE, A_DIM);   // (4, 2, 512) = 4096 blocks
    dim3 block(NTHREADS);
    parafac_mma_kernel<<<grid, block>>>(f0, f1, f2, out);
}